// round 1
// baseline (speedup 1.0000x reference)
#include <cuda_runtime.h>
#include <cuda_bf16.h>
#include <cstdint>

// Problem constants
#define B_ROWS 16384
#define N_CLS  1000
#define KPC    4          // centroids per class
#define NSIM   4000       // N_CLS * KPC
#define NPAD   4096       // padded sim columns
#define D      64         // feature dim

// Tile config
#define TM 128            // rows per CTA
#define TN 128            // sim cols per CTA
#define THREADS 256

// bf16 normalized-centroid scratch, padded (rows 4000..4095 stay zero)
__device__ __nv_bfloat16 g_B[NPAD * D];

// SW128 swizzle on byte offsets (rows are exactly 128 bytes)
__device__ __forceinline__ uint32_t sw128(uint32_t off) {
    return off ^ ((off >> 3) & 0x70);
}

// ---------------------------------------------------------------------------
// Kernel 1: L2-normalize centroids (fp32) -> bf16 scratch
// one warp per centroid vector (4000 vectors x 64 elems)
// ---------------------------------------------------------------------------
__global__ void norm_centroids_kernel(const float* __restrict__ cents) {
    int r = blockIdx.x;                 // 0..3999
    int lane = threadIdx.x;             // 0..31
    float v0 = cents[r * D + lane];
    float v1 = cents[r * D + 32 + lane];
    float ss = v0 * v0 + v1 * v1;
#pragma unroll
    for (int o = 16; o > 0; o >>= 1)
        ss += __shfl_xor_sync(0xFFFFFFFFu, ss, o);
    float inv = 1.0f / fmaxf(sqrtf(ss), 1e-12f);
    g_B[r * D + lane]      = __float2bfloat16(v0 * inv);
    g_B[r * D + 32 + lane] = __float2bfloat16(v1 * inv);
}

// ---------------------------------------------------------------------------
// Kernel 2: sim = codes @ centsT (bf16 mma.sync), fused min-over-K epilogue
// CTA tile: 128 rows x 128 sim-cols (= 32 classes). 8 warps: 2(M) x 4(N).
// Each warp: 64x32 via m16n8k16 -> 4 m-tiles x 4 n-tiles.
// ---------------------------------------------------------------------------
__global__ __launch_bounds__(THREADS)
void gemm_min_kernel(const float* __restrict__ codes, float* __restrict__ out) {
    __shared__ union {
        struct {
            __nv_bfloat16 A[TM * D];    // 16 KB, SW128-swizzled
            __nv_bfloat16 Bm[TN * D];   // 16 KB, SW128-swizzled
        } ab;
        float sims[64 * 132];           // 33.8 KB epilogue buffer (reused)
    } sm;

    const int tid  = threadIdx.x;
    const int lane = tid & 31;
    const int wid  = tid >> 5;
    const int wm   = wid >> 2;          // 0..1 (64-row slab)
    const int wn   = wid & 3;           // 0..3 (32-col slab)

    const int row0 = blockIdx.y * TM;   // code row base
    const int col0 = blockIdx.x * TN;   // sim col base

    // ---- load A tile: fp32 codes -> bf16 swizzled smem ----
    {
        char* ap = (char*)sm.ab.A;
#pragma unroll
        for (int it = 0; it < 8; it++) {
            int idx = tid + it * THREADS;        // 0..2047 float4s
            int r  = idx >> 4;                   // row 0..127
            int cg = idx & 15;                   // float4 index in row
            float4 v = *(const float4*)(codes + (size_t)(row0 + r) * D + cg * 4);
            uint32_t off = sw128((uint32_t)(r * 128 + cg * 8));
            __nv_bfloat162 p0 = __floats2bfloat162_rn(v.x, v.y);
            __nv_bfloat162 p1 = __floats2bfloat162_rn(v.z, v.w);
            *(__nv_bfloat162*)(ap + off)     = p0;
            *(__nv_bfloat162*)(ap + off + 4) = p1;
        }
    }
    // ---- load B tile: bf16 scratch -> swizzled smem (16B vectors) ----
    {
        char* bp = (char*)sm.ab.Bm;
#pragma unroll
        for (int it = 0; it < 4; it++) {
            int idx = tid + it * THREADS;        // 0..1023 uint4s
            int r  = idx >> 3;                   // n row 0..127
            int ch = idx & 7;                    // 16B chunk in row
            uint4 v = *(const uint4*)(g_B + (size_t)(col0 + r) * D + ch * 8);
            *(uint4*)(bp + sw128((uint32_t)(r * 128 + ch * 16))) = v;
        }
    }
    __syncthreads();

    uint32_t aBase = (uint32_t)__cvta_generic_to_shared(sm.ab.A);
    uint32_t bBase = (uint32_t)__cvta_generic_to_shared(sm.ab.Bm);

    float acc[4][4][4];
#pragma unroll
    for (int i = 0; i < 4; i++)
#pragma unroll
        for (int j = 0; j < 4; j++)
#pragma unroll
            for (int c = 0; c < 4; c++) acc[i][j][c] = 0.0f;

    const int g  = lane >> 3;       // ldmatrix lane group 0..3
    const int lr = lane & 7;
    const int rAdd = lr + ((g & 1) << 3);        // row offset within 16
    const int kAdd = ((g >> 1) << 3) * 2;        // byte offset (+0 or +16B)

#pragma unroll
    for (int ks = 0; ks < 4; ks++) {
        const int kb = ks * 32 + kAdd;           // byte offset of k chunk
        uint32_t af[4][4];
        uint32_t bfm[4][2];
        // A fragments: 4 m-tiles (non-trans ldmatrix.x4)
#pragma unroll
        for (int i = 0; i < 4; i++) {
            int row = wm * 64 + i * 16 + rAdd;
            uint32_t addr = aBase + sw128((uint32_t)(row * 128 + kb));
            asm volatile(
                "ldmatrix.sync.aligned.m8n8.x4.shared.b16 {%0,%1,%2,%3}, [%4];"
                : "=r"(af[i][0]), "=r"(af[i][1]), "=r"(af[i][2]), "=r"(af[i][3])
                : "r"(addr));
        }
        // B fragments: B stored [n][k] row-major == col-major kxn -> non-trans
        // ldmatrix.x4 covers 16 n-rows: tile0={r0,r2}, tile1={r1,r3}
#pragma unroll
        for (int h = 0; h < 2; h++) {
            int nrow = wn * 32 + h * 16 + rAdd;
            uint32_t addr = bBase + sw128((uint32_t)(nrow * 128 + kb));
            uint32_t r0, r1, r2, r3;
            asm volatile(
                "ldmatrix.sync.aligned.m8n8.x4.shared.b16 {%0,%1,%2,%3}, [%4];"
                : "=r"(r0), "=r"(r1), "=r"(r2), "=r"(r3)
                : "r"(addr));
            bfm[h * 2 + 0][0] = r0; bfm[h * 2 + 0][1] = r2;
            bfm[h * 2 + 1][0] = r1; bfm[h * 2 + 1][1] = r3;
        }
#pragma unroll
        for (int i = 0; i < 4; i++)
#pragma unroll
            for (int j = 0; j < 4; j++) {
                asm volatile(
                    "mma.sync.aligned.m16n8k16.row.col.f32.bf16.bf16.f32 "
                    "{%0,%1,%2,%3}, {%4,%5,%6,%7}, {%8,%9}, {%0,%1,%2,%3};"
                    : "+f"(acc[i][j][0]), "+f"(acc[i][j][1]),
                      "+f"(acc[i][j][2]), "+f"(acc[i][j][3])
                    : "r"(af[i][0]), "r"(af[i][1]), "r"(af[i][2]), "r"(af[i][3]),
                      "r"(bfm[j][0]), "r"(bfm[j][1]));
            }
    }
    __syncthreads();   // all smem A/B reads done; safe to alias with sims

    // ---- epilogue in two 64-row phases ----
    const int fr = lane >> 2;            // 0..7 fragment row
    const int fc = (lane & 3) * 2;       // fragment col pair
#pragma unroll
    for (int ph = 0; ph < 2; ph++) {
        if (wm == ph) {
#pragma unroll
            for (int i = 0; i < 4; i++)
#pragma unroll
                for (int j = 0; j < 4; j++) {
                    int r  = i * 16 + fr;
                    int cb = wn * 32 + j * 8 + fc;
                    *(float2*)&sm.sims[r * 132 + cb] =
                        make_float2(acc[i][j][0], acc[i][j][1]);
                    *(float2*)&sm.sims[(r + 8) * 132 + cb] =
                        make_float2(acc[i][j][2], acc[i][j][3]);
                }
        }
        __syncthreads();
        // reduce: 64 rows x 32 classes, max over 4 sims -> out = 1 - max
#pragma unroll
        for (int t = tid; t < 64 * 32; t += THREADS) {
            int r   = t >> 5;
            int cls = t & 31;
            float4 v = *(float4*)&sm.sims[r * 132 + cls * 4];
            float mx = fmaxf(fmaxf(v.x, v.y), fmaxf(v.z, v.w));
            int gr = row0 + ph * 64 + r;
            int gc = blockIdx.x * (TN / KPC) + cls;
            if (gc < N_CLS)
                out[(size_t)gr * N_CLS + gc] = 1.0f - mx;
        }
        __syncthreads();
    }
}

// ---------------------------------------------------------------------------
extern "C" void kernel_launch(void* const* d_in, const int* in_sizes, int n_in,
                              void* d_out, int out_size) {
    const float* codes = (const float*)d_in[0];      // (16384, 64)
    const float* cents = (const float*)d_in[1];      // (1000, 4, 64)
    float* out = (float*)d_out;                      // (16384, 1000)

    norm_centroids_kernel<<<NSIM, 32>>>(cents);

    dim3 grid(NPAD / TN, B_ROWS / TM);               // (32, 128)
    gemm_min_kernel<<<grid, THREADS>>>(codes, out);
}

// round 2
// speedup vs baseline: 1.2265x; 1.2265x over previous
#include <cuda_runtime.h>
#include <cuda_bf16.h>
#include <cstdint>

// Problem constants
#define B_ROWS 16384
#define N_CLS  1000
#define KPC    4
#define NSIM   4000
#define NPAD   4096
#define D      64

#define TM 128
#define TN 128
#define THREADS 256

// bf16 scratch: normalized centroids (padded; rows 4000..4095 stay zero),
// and codes converted to bf16.
__device__ __nv_bfloat16 g_B[NPAD * D];
__device__ __nv_bfloat16 g_A[B_ROWS * D];

__device__ __forceinline__ uint32_t sw128(uint32_t off) {
    return off ^ ((off >> 3) & 0x70);
}

// ---------------------------------------------------------------------------
// Prep 1: L2-normalize centroids (fp32) -> bf16 scratch. One warp per vector.
// ---------------------------------------------------------------------------
__global__ void norm_centroids_kernel(const float* __restrict__ cents) {
    int r = blockIdx.x;
    int lane = threadIdx.x;
    float v0 = cents[r * D + lane];
    float v1 = cents[r * D + 32 + lane];
    float ss = v0 * v0 + v1 * v1;
#pragma unroll
    for (int o = 16; o > 0; o >>= 1)
        ss += __shfl_xor_sync(0xFFFFFFFFu, ss, o);
    float inv = 1.0f / fmaxf(sqrtf(ss), 1e-12f);
    g_B[r * D + lane]      = __float2bfloat16(v0 * inv);
    g_B[r * D + 32 + lane] = __float2bfloat16(v1 * inv);
}

// ---------------------------------------------------------------------------
// Prep 2: codes fp32 -> bf16 scratch (already normalized).
// ---------------------------------------------------------------------------
__global__ void convert_codes_kernel(const float* __restrict__ codes) {
    int idx = blockIdx.x * blockDim.x + threadIdx.x;   // float4 index
    float4 v = *(const float4*)(codes + (size_t)idx * 4);
    __nv_bfloat162 p0 = __floats2bfloat162_rn(v.x, v.y);
    __nv_bfloat162 p1 = __floats2bfloat162_rn(v.z, v.w);
    *(__nv_bfloat162*)(g_A + (size_t)idx * 4)     = p0;
    *(__nv_bfloat162*)(g_A + (size_t)idx * 4 + 2) = p1;
}

// ---------------------------------------------------------------------------
// GEMM + fused min-over-K. CTA: 128 rows x 128 sim-cols (32 classes).
// 8 warps: 2(M) x 4(N); warp tile 64x32 via m16n8k16.
// Epilogue: register max-reduce + tiny smem transpose for coalesced stores.
// ---------------------------------------------------------------------------
__global__ __launch_bounds__(THREADS)
void gemm_min_kernel(float* __restrict__ out) {
    __shared__ union {
        struct {
            __nv_bfloat16 A[TM * D];     // 16 KB SW128-swizzled
            __nv_bfloat16 Bm[TN * D];    // 16 KB SW128-swizzled
        } ab;
        float red[TM * 33];              // 16.9 KB reduced results (reused)
    } sm;

    const int tid  = threadIdx.x;
    const int lane = tid & 31;
    const int wid  = tid >> 5;
    const int wm   = wid >> 2;
    const int wn   = wid & 3;

    const int row0 = blockIdx.y * TM;
    const int col0 = blockIdx.x * TN;

    // ---- cp.async both tiles (bf16, 16B chunks) ----
    {
        uint32_t aB = (uint32_t)__cvta_generic_to_shared(sm.ab.A);
        uint32_t bB = (uint32_t)__cvta_generic_to_shared(sm.ab.Bm);
#pragma unroll
        for (int it = 0; it < 4; it++) {
            int idx = tid + it * THREADS;          // 0..1023
            int r  = idx >> 3;
            int ch = idx & 7;
            uint32_t dst = aB + sw128((uint32_t)(r * 128 + ch * 16));
            const __nv_bfloat16* src = g_A + (size_t)(row0 + r) * D + ch * 8;
            asm volatile("cp.async.cg.shared.global [%0], [%1], 16;\n"
                         :: "r"(dst), "l"(src));
        }
#pragma unroll
        for (int it = 0; it < 4; it++) {
            int idx = tid + it * THREADS;
            int r  = idx >> 3;
            int ch = idx & 7;
            uint32_t dst = bB + sw128((uint32_t)(r * 128 + ch * 16));
            const __nv_bfloat16* src = g_B + (size_t)(col0 + r) * D + ch * 8;
            asm volatile("cp.async.cg.shared.global [%0], [%1], 16;\n"
                         :: "r"(dst), "l"(src));
        }
        asm volatile("cp.async.commit_group;\n" ::);
        asm volatile("cp.async.wait_group 0;\n" ::);
    }
    __syncthreads();

    uint32_t aBase = (uint32_t)__cvta_generic_to_shared(sm.ab.A);
    uint32_t bBase = (uint32_t)__cvta_generic_to_shared(sm.ab.Bm);

    float acc[4][4][4];
#pragma unroll
    for (int i = 0; i < 4; i++)
#pragma unroll
        for (int j = 0; j < 4; j++)
#pragma unroll
            for (int c = 0; c < 4; c++) acc[i][j][c] = 0.0f;

    const int g  = lane >> 3;
    const int lr = lane & 7;
    const int rAdd = lr + ((g & 1) << 3);
    const int kAdd = ((g >> 1) << 3) * 2;

#pragma unroll
    for (int ks = 0; ks < 4; ks++) {
        const int kb = ks * 32 + kAdd;
        uint32_t af[4][4];
        uint32_t bfm[4][2];
#pragma unroll
        for (int i = 0; i < 4; i++) {
            int row = wm * 64 + i * 16 + rAdd;
            uint32_t addr = aBase + sw128((uint32_t)(row * 128 + kb));
            asm volatile(
                "ldmatrix.sync.aligned.m8n8.x4.shared.b16 {%0,%1,%2,%3}, [%4];"
                : "=r"(af[i][0]), "=r"(af[i][1]), "=r"(af[i][2]), "=r"(af[i][3])
                : "r"(addr));
        }
#pragma unroll
        for (int h = 0; h < 2; h++) {
            int nrow = wn * 32 + h * 16 + rAdd;
            uint32_t addr = bBase + sw128((uint32_t)(nrow * 128 + kb));
            uint32_t r0, r1, r2, r3;
            asm volatile(
                "ldmatrix.sync.aligned.m8n8.x4.shared.b16 {%0,%1,%2,%3}, [%4];"
                : "=r"(r0), "=r"(r1), "=r"(r2), "=r"(r3)
                : "r"(addr));
            bfm[h * 2 + 0][0] = r0; bfm[h * 2 + 0][1] = r2;
            bfm[h * 2 + 1][0] = r1; bfm[h * 2 + 1][1] = r3;
        }
        // non-volatile: let ptxas interleave MMAs with next-step LDSMs
#pragma unroll
        for (int i = 0; i < 4; i++)
#pragma unroll
            for (int j = 0; j < 4; j++) {
                asm("mma.sync.aligned.m16n8k16.row.col.f32.bf16.bf16.f32 "
                    "{%0,%1,%2,%3}, {%4,%5,%6,%7}, {%8,%9}, {%0,%1,%2,%3};"
                    : "+f"(acc[i][j][0]), "+f"(acc[i][j][1]),
                      "+f"(acc[i][j][2]), "+f"(acc[i][j][3])
                    : "r"(af[i][0]), "r"(af[i][1]), "r"(af[i][2]), "r"(af[i][3]),
                      "r"(bfm[j][0]), "r"(bfm[j][1]));
            }
    }
    __syncthreads();   // smem A/B reads done; safe to alias with red

    // ---- register max-over-4 reduction, stage reduced values in smem ----
    const int fr = lane >> 2;              // fragment row 0..7
    const int clsbit = (lane >> 1) & 1;    // which class of the n8 tile
    const bool writer = (lane & 1) == 0;
#pragma unroll
    for (int i = 0; i < 4; i++) {
#pragma unroll
        for (int j = 0; j < 4; j++) {
            float mlo = fmaxf(acc[i][j][0], acc[i][j][1]);
            float mhi = fmaxf(acc[i][j][2], acc[i][j][3]);
            mlo = fmaxf(mlo, __shfl_xor_sync(0xFFFFFFFFu, mlo, 1));
            mhi = fmaxf(mhi, __shfl_xor_sync(0xFFFFFFFFu, mhi, 1));
            if (writer) {
                int r   = wm * 64 + i * 16 + fr;
                int cls = wn * 8 + j * 2 + clsbit;
                sm.red[r * 33 + cls]       = mlo;
                sm.red[(r + 8) * 33 + cls] = mhi;
            }
        }
    }
    __syncthreads();

    // ---- coalesced stores: 128 rows x 32 classes ----
    const int cbase = blockIdx.x * 32;
#pragma unroll
    for (int t = tid; t < TM * 32; t += THREADS) {
        int r   = t >> 5;
        int cls = t & 31;
        int gc  = cbase + cls;
        if (gc < N_CLS)
            out[(size_t)(row0 + r) * N_CLS + gc] = 1.0f - sm.red[r * 33 + cls];
    }
}

// ---------------------------------------------------------------------------
extern "C" void kernel_launch(void* const* d_in, const int* in_sizes, int n_in,
                              void* d_out, int out_size) {
    const float* codes = (const float*)d_in[0];      // (16384, 64)
    const float* cents = (const float*)d_in[1];      // (1000, 4, 64)
    float* out = (float*)d_out;                      // (16384, 1000)

    norm_centroids_kernel<<<NSIM, 32>>>(cents);
    convert_codes_kernel<<<(B_ROWS * D / 4) / 256, 256>>>(codes);

    dim3 grid(NPAD / TN, B_ROWS / TM);               // (32, 128)
    gemm_min_kernel<<<grid, THREADS>>>(out);
}